// round 1
// baseline (speedup 1.0000x reference)
#include <cuda_runtime.h>

// Problem constants
#define B_      32
#define E_      5
#define CIN_    256
#define COUT_   256
#define HH      56
#define WW      56
#define HW      (HH * WW)          // 3136
#define M_PER_OC 2304              // CIN*3*3
#define SCALING 4.0f               // 16.0 / R, R=4
#define CI_TILE 8

// Scratch (device globals; no cudaMalloc allowed)
__device__ int   g_expert[B_];
// Aggregated per-expert weights in TRANSPOSED layout: [e][ocb(4)][m(2304)][ocl(64)]
__device__ float g_aggw[E_ * 4 * M_PER_OC * 64];

// ---------------------------------------------------------------------------
// Kernel 1: top-1 expert per sample (first-max semantics like jnp.argmax)
// ---------------------------------------------------------------------------
__global__ void expert_kernel(const float* __restrict__ scores) {
    int b = threadIdx.x;
    if (b < B_) {
        const float* s = scores + b * E_;
        float best = s[0];
        int bi = 0;
#pragma unroll
        for (int e = 1; e < E_; ++e) {
            float v = s[e];
            if (v > best) { best = v; bi = e; }
        }
        g_expert[b] = bi;
    }
}

// ---------------------------------------------------------------------------
// Kernel 2: aggw[e][ocb][m][ocl] = W[oc][m] + SCALING * sum_r B[e,3oc+m/768,r]*A[e,r,m%768]
// Thread mapping keeps m fastest-varying -> coalesced reads of weight & lora_A.
// ---------------------------------------------------------------------------
__global__ void aggw_kernel(const float* __restrict__ weight,
                            const float* __restrict__ lora_A,
                            const float* __restrict__ lora_B) {
    int t = blockIdx.x * blockDim.x + threadIdx.x;   // total 5*256*2304 = 2,949,120
    int m    = t % M_PER_OC;
    int rest = t / M_PER_OC;
    int oc   = rest % COUT_;
    int e    = rest / COUT_;
    if (e >= E_) return;

    int j = m / 768;   // ok = 3*oc + j
    int v = m % 768;   // ik

    const float* Bp = lora_B + e * 9216 + (3 * oc + j) * 12;
    const float* Ap = lora_A + e * 9216;

    float acc = 0.f;
#pragma unroll
    for (int r = 0; r < 12; ++r)
        acc += Bp[r] * Ap[r * 768 + v];

    float w = weight[oc * M_PER_OC + m];
    int ocb = oc >> 6, ocl = oc & 63;
    g_aggw[(((e * 4 + ocb) * M_PER_OC) + m) * 64 + ocl] = w + SCALING * acc;
}

// ---------------------------------------------------------------------------
// Packed fp32x2 helpers (sm_100+): doubles fp32 FMA throughput
// ---------------------------------------------------------------------------
__device__ __forceinline__ unsigned long long pk2(float lo, float hi) {
    unsigned long long r;
    asm("mov.b64 %0, {%1,%2};" : "=l"(r) : "f"(lo), "f"(hi));
    return r;
}
__device__ __forceinline__ void fma2(unsigned long long& d,
                                     unsigned long long a,
                                     unsigned long long b) {
    asm("fma.rn.f32x2 %0, %1, %2, %0;" : "+l"(d) : "l"(a), "l"(b));
}
__device__ __forceinline__ float2 up2(unsigned long long v) {
    float lo, hi;
    asm("mov.b64 {%0,%1}, %2;" : "=f"(lo), "=f"(hi) : "l"(v));
    return make_float2(lo, hi);
}

// ---------------------------------------------------------------------------
// Kernel 3: direct conv. Grid (49 tiles, 4 ocb, 32 b), 128 threads.
// CTA computes 64 output channels x 8x8 pixels. Thread: 4 oc x (2 rows x 4 cols).
// ---------------------------------------------------------------------------
__global__ __launch_bounds__(128)
void conv_kernel(const float* __restrict__ x, float* __restrict__ out) {
    __shared__ __align__(16) float w_s[CI_TILE * 9 * 64];  // [m][oc], 18 KB
    __shared__ __align__(16) float x_s[CI_TILE * 100];     // [ci][10][10], 3.2 KB

    const int tile = blockIdx.x;          // 0..48
    const int ocb  = blockIdx.y;          // 0..3
    const int b    = blockIdx.z;          // 0..31
    const int gy0  = (tile / 7) * 8;
    const int gx0  = (tile % 7) * 8;
    const int e    = g_expert[b];
    const int tid  = threadIdx.x;

    const float* xb = x + (long long)b * CIN_ * HW;
    const float* wg = g_aggw + (long long)(e * 4 + ocb) * M_PER_OC * 64;

    const int chid = tid & 15;            // 16 channel-slots
    const int pxid = tid >> 4;            // 8 pixel-slots
    const int oc0  = chid * 4;
    const int py0  = (pxid >> 1) * 2;     // 0,2,4,6
    const int px0  = (pxid & 1) * 4;      // 0,4

    unsigned long long acc[16];
#pragma unroll
    for (int i = 0; i < 16; ++i) acc[i] = 0ULL;

    for (int ci0 = 0; ci0 < CIN_; ci0 += CI_TILE) {
        // --- load weight slab: 72 m-rows x 64 oc = 4608 floats (coalesced, no conflicts)
        const float4* wg4 = (const float4*)(wg + ci0 * 9 * 64);
        float4* ws4 = (float4*)w_s;
#pragma unroll
        for (int i = 0; i < 9; ++i)
            ws4[tid + i * 128] = wg4[tid + i * 128];

        // --- load x tile: 8 ci x 10 x 10 (halo, zero padded)
#pragma unroll
        for (int i = 0; i < 7; ++i) {
            int idx = tid + i * 128;
            if (idx < CI_TILE * 100) {
                int ci  = idx / 100;
                int rem = idx - ci * 100;
                int rr  = rem / 10;
                int cc  = rem - rr * 10;
                int gy  = gy0 - 1 + rr;
                int gx  = gx0 - 1 + cc;
                float val = 0.f;
                if (gy >= 0 && gy < HH && gx >= 0 && gx < WW)
                    val = xb[(ci0 + ci) * HW + gy * WW + gx];
                x_s[idx] = val;
            }
        }
        __syncthreads();

#pragma unroll 4
        for (int ci = 0; ci < CI_TILE; ++ci) {
            const float* xr = x_s + ci * 100;
#pragma unroll
            for (int k1 = 0; k1 < 3; ++k1) {
                const float* xr0 = xr + (py0 + k1) * 10 + px0;
                const float* xr1 = xr0 + 10;
#pragma unroll
                for (int k2 = 0; k2 < 3; ++k2) {
                    int m = ci * 9 + k1 * 3 + k2;
                    float4 wv = *(const float4*)(w_s + m * 64 + oc0);
                    unsigned long long wd0 = pk2(wv.x, wv.x);
                    unsigned long long wd1 = pk2(wv.y, wv.y);
                    unsigned long long wd2 = pk2(wv.z, wv.z);
                    unsigned long long wd3 = pk2(wv.w, wv.w);
                    unsigned long long xa0 = pk2(xr0[k2],     xr0[k2 + 1]);
                    unsigned long long xa1 = pk2(xr0[k2 + 2], xr0[k2 + 3]);
                    unsigned long long xb0 = pk2(xr1[k2],     xr1[k2 + 1]);
                    unsigned long long xb1 = pk2(xr1[k2 + 2], xr1[k2 + 3]);
                    fma2(acc[0],  wd0, xa0); fma2(acc[1],  wd0, xa1);
                    fma2(acc[2],  wd0, xb0); fma2(acc[3],  wd0, xb1);
                    fma2(acc[4],  wd1, xa0); fma2(acc[5],  wd1, xa1);
                    fma2(acc[6],  wd1, xb0); fma2(acc[7],  wd1, xb1);
                    fma2(acc[8],  wd2, xa0); fma2(acc[9],  wd2, xa1);
                    fma2(acc[10], wd2, xb0); fma2(acc[11], wd2, xb1);
                    fma2(acc[12], wd3, xa0); fma2(acc[13], wd3, xa1);
                    fma2(acc[14], wd3, xb0); fma2(acc[15], wd3, xb1);
                }
            }
        }
        __syncthreads();
    }

    // --- epilogue: 4 oc x 2 rows x 4 cols per thread, contiguous float2 stores
#pragma unroll
    for (int o = 0; o < 4; ++o) {
        int oc = ocb * 64 + oc0 + o;
#pragma unroll
        for (int r = 0; r < 2; ++r) {
            int y = gy0 + py0 + r;
            float* op = out + (((long long)b * COUT_ + oc) * HH + y) * WW + gx0 + px0;
            float2 v0 = up2(acc[o * 4 + r * 2 + 0]);
            float2 v1 = up2(acc[o * 4 + r * 2 + 1]);
            *(float2*)(op)     = v0;
            *(float2*)(op + 2) = v1;
        }
    }
}

// ---------------------------------------------------------------------------
extern "C" void kernel_launch(void* const* d_in, const int* in_sizes, int n_in,
                              void* d_out, int out_size) {
    const float* x      = (const float*)d_in[0];
    const float* scores = (const float*)d_in[1];
    const float* weight = (const float*)d_in[2];
    const float* lora_A = (const float*)d_in[3];
    const float* lora_B = (const float*)d_in[4];
    float* out = (float*)d_out;

    expert_kernel<<<1, 32>>>(scores);

    int total = E_ * COUT_ * M_PER_OC;           // 2,949,120
    aggw_kernel<<<total / 256, 256>>>(weight, lora_A, lora_B);

    dim3 grid(49, 4, B_);
    conv_kernel<<<grid, 128>>>(x, out);
}

// round 2
// speedup vs baseline: 1.2168x; 1.2168x over previous
#include <cuda_runtime.h>

// Problem constants
#define B_      32
#define E_      5
#define CIN_    256
#define COUT_   256
#define HH      56
#define WW      56
#define HW      (HH * WW)          // 3136
#define M_PER_OC 2304              // CIN*3*3
#define SCALING 4.0f               // 16.0 / R, R=4
#define CI_TILE 8

typedef unsigned long long u64;

// Scratch (device globals; no cudaMalloc allowed)
__device__ int   g_expert[B_];
// Aggregated per-expert weights TRANSPOSED: [e][ocb(4)][m(2304)][ocl(64)]
__device__ float g_aggw[E_ * 4 * M_PER_OC * 64];

// ---------------------------------------------------------------------------
// Kernel 1: top-1 expert per sample (first-max semantics like jnp.argmax)
// ---------------------------------------------------------------------------
__global__ void expert_kernel(const float* __restrict__ scores) {
    int b = threadIdx.x;
    if (b < B_) {
        const float* s = scores + b * E_;
        float best = s[0];
        int bi = 0;
#pragma unroll
        for (int e = 1; e < E_; ++e) {
            float v = s[e];
            if (v > best) { best = v; bi = e; }
        }
        g_expert[b] = bi;
    }
}

// ---------------------------------------------------------------------------
// Kernel 2: aggw[e][ocb][m][ocl] = W[oc][m] + SCALING * sum_r B[e,3oc+m/768,r]*A[e,r,m%768]
// ---------------------------------------------------------------------------
__global__ void aggw_kernel(const float* __restrict__ weight,
                            const float* __restrict__ lora_A,
                            const float* __restrict__ lora_B) {
    int t = blockIdx.x * blockDim.x + threadIdx.x;   // 5*256*2304 = 2,949,120
    int m    = t % M_PER_OC;
    int rest = t / M_PER_OC;
    int oc   = rest % COUT_;
    int e    = rest / COUT_;
    if (e >= E_) return;

    int j = m / 768;   // ok = 3*oc + j
    int v = m % 768;   // ik

    const float* Bp = lora_B + e * 9216 + (3 * oc + j) * 12;
    const float* Ap = lora_A + e * 9216;

    float acc = 0.f;
#pragma unroll
    for (int r = 0; r < 12; ++r)
        acc += Bp[r] * Ap[r * 768 + v];

    float w = weight[oc * M_PER_OC + m];
    int ocb = oc >> 6, ocl = oc & 63;
    g_aggw[(((e * 4 + ocb) * M_PER_OC) + m) * 64 + ocl] = w + SCALING * acc;
}

// ---------------------------------------------------------------------------
// Packed fp32x2 helpers
// ---------------------------------------------------------------------------
__device__ __forceinline__ u64 dup2(float v) {
    u64 r;
    asm("mov.b64 %0, {%1,%1};" : "=l"(r) : "f"(v));
    return r;
}
__device__ __forceinline__ void fma2(u64& d, u64 a, u64 b) {
    asm("fma.rn.f32x2 %0, %1, %2, %0;" : "+l"(d) : "l"(a), "l"(b));
}
__device__ __forceinline__ float2 up2(u64 v) {
    float lo, hi;
    asm("mov.b64 {%0,%1}, %2;" : "=f"(lo), "=f"(hi) : "l"(v));
    return make_float2(lo, hi);
}
// LDS.128 delivering two aligned f32x2 pairs directly (no repacking MOVs)
__device__ __forceinline__ void lds_w2(u64& a, u64& b, unsigned addr) {
    asm("ld.shared.v2.u64 {%0,%1}, [%2];" : "=l"(a), "=l"(b) : "r"(addr));
}

// ---------------------------------------------------------------------------
// Kernel 3: direct conv. Grid (49 tiles, 4 ocb, 32 b), 64 threads.
// CTA: 64 oc x 8x8 px. Thread: 8 oc (4 f32x2 pairs) x 8 px (one row).
// ---------------------------------------------------------------------------
__global__ __launch_bounds__(64)
void conv_kernel(const float* __restrict__ x, float* __restrict__ out) {
    __shared__ __align__(16) float w_s[CI_TILE * 9 * 64];   // [m][oc], 18 KB
    __shared__ __align__(16) float x_s[CI_TILE * 10 * 12];  // [ci][10 rows][12], 3.75 KB

    const int tile = blockIdx.x;          // 0..48
    const int ocb  = blockIdx.y;          // 0..3
    const int b    = blockIdx.z;          // 0..31
    const int gy0  = (tile / 7) * 8;
    const int gx0  = (tile % 7) * 8;
    const int e    = g_expert[b];
    const int tid  = threadIdx.x;

    const int chid = tid & 7;             // 8 oc-slots
    const int row  = tid >> 3;            // 8 row-slots
    const int oc0  = chid * 8;

    const float* xb = x + (long long)b * CIN_ * HW;
    const float* wg = g_aggw + (long long)(e * 4 + ocb) * M_PER_OC * 64;

    u64 acc[32];
#pragma unroll
    for (int i = 0; i < 32; ++i) acc[i] = 0ULL;

    const unsigned w_sbase = (unsigned)__cvta_generic_to_shared(w_s) + oc0 * 4;
    const float* xrow_base = x_s + row * 12;

    for (int ci0 = 0; ci0 < CIN_; ci0 += CI_TILE) {
        // --- weight slab: 72 m-rows x 64 oc = 4608 floats (1152 float4, coalesced)
        const float4* wg4 = (const float4*)(wg + ci0 * 9 * 64);
        float4* ws4 = (float4*)w_s;
#pragma unroll
        for (int i = 0; i < 18; ++i)
            ws4[tid + i * 64] = wg4[tid + i * 64];

        // --- x slab: 8 ci x 10 x 10 halo in 8 x 10 x 12 padded layout (960 slots)
#pragma unroll
        for (int i = 0; i < 15; ++i) {
            int idx = tid + i * 64;
            int ci  = idx / 120;
            int rem = idx - ci * 120;
            int rr  = rem / 12;
            int cc  = rem - rr * 12;
            int gy  = gy0 - 1 + rr;
            int gx  = gx0 - 1 + cc;
            float val = 0.f;
            if (cc < 10 && gy >= 0 && gy < HH && gx >= 0 && gx < WW)
                val = xb[(ci0 + ci) * HW + gy * WW + gx];
            x_s[idx] = val;
        }
        __syncthreads();

#pragma unroll 1
        for (int ci = 0; ci < CI_TILE; ++ci) {
            const float* xp = xrow_base + ci * 120;
            const unsigned wbase = w_sbase + (ci * 9) * 256;   // 64 floats * 4B per m-row
#pragma unroll
            for (int k1 = 0; k1 < 3; ++k1) {
                // sliding window: 10 halo floats of this row, loaded as 3 LDS.128
                const float4* xq = (const float4*)(xp + k1 * 12);
                float4 q0 = xq[0], q1 = xq[1], q2 = xq[2];
                u64 xd[10];
                xd[0] = dup2(q0.x); xd[1] = dup2(q0.y);
                xd[2] = dup2(q0.z); xd[3] = dup2(q0.w);
                xd[4] = dup2(q1.x); xd[5] = dup2(q1.y);
                xd[6] = dup2(q1.z); xd[7] = dup2(q1.w);
                xd[8] = dup2(q2.x); xd[9] = dup2(q2.y);
#pragma unroll
                for (int k2 = 0; k2 < 3; ++k2) {
                    unsigned wa = wbase + (k1 * 3 + k2) * 256;
                    u64 wp0, wp1, wp2, wp3;
                    lds_w2(wp0, wp1, wa);
                    lds_w2(wp2, wp3, wa + 16);
#pragma unroll
                    for (int j = 0; j < 8; ++j) {
                        fma2(acc[j],      wp0, xd[k2 + j]);
                        fma2(acc[8 + j],  wp1, xd[k2 + j]);
                        fma2(acc[16 + j], wp2, xd[k2 + j]);
                        fma2(acc[24 + j], wp3, xd[k2 + j]);
                    }
                }
            }
        }
        __syncthreads();
    }

    // --- epilogue: 4 oc-pairs x 8 px; assemble float4 rows, STG.128
    const int y = gy0 + row;
#pragma unroll
    for (int p = 0; p < 4; ++p) {
        const int oc = ocb * 64 + oc0 + 2 * p;
        float2 a0 = up2(acc[p * 8 + 0]), a1 = up2(acc[p * 8 + 1]);
        float2 a2 = up2(acc[p * 8 + 2]), a3 = up2(acc[p * 8 + 3]);
        float2 a4 = up2(acc[p * 8 + 4]), a5 = up2(acc[p * 8 + 5]);
        float2 a6 = up2(acc[p * 8 + 6]), a7 = up2(acc[p * 8 + 7]);
        float* o0 = out + (((long long)b * COUT_ + oc) * HH + y) * WW + gx0;
        float* o1 = o0 + HW;
        ((float4*)o0)[0] = make_float4(a0.x, a1.x, a2.x, a3.x);
        ((float4*)o0)[1] = make_float4(a4.x, a5.x, a6.x, a7.x);
        ((float4*)o1)[0] = make_float4(a0.y, a1.y, a2.y, a3.y);
        ((float4*)o1)[1] = make_float4(a4.y, a5.y, a6.y, a7.y);
    }
}

// ---------------------------------------------------------------------------
extern "C" void kernel_launch(void* const* d_in, const int* in_sizes, int n_in,
                              void* d_out, int out_size) {
    const float* x      = (const float*)d_in[0];
    const float* scores = (const float*)d_in[1];
    const float* weight = (const float*)d_in[2];
    const float* lora_A = (const float*)d_in[3];
    const float* lora_B = (const float*)d_in[4];
    float* out = (float*)d_out;

    expert_kernel<<<1, 32>>>(scores);

    int total = E_ * COUT_ * M_PER_OC;           // 2,949,120
    aggw_kernel<<<total / 256, 256>>>(weight, lora_A, lora_B);

    dim3 grid(49, 4, B_);
    conv_kernel<<<grid, 64>>>(x, out);
}

// round 3
// speedup vs baseline: 1.2180x; 1.0010x over previous
#include <cuda_runtime.h>

// Problem constants
#define B_      32
#define E_      5
#define CIN_    256
#define COUT_   256
#define HH      56
#define WW      56
#define HW      (HH * WW)          // 3136
#define M_PER_OC 2304              // CIN*3*3
#define SCALING 4.0f               // 16.0 / R, R=4
#define CI_TILE 8

typedef unsigned long long u64;

// Scratch (device globals; no cudaMalloc allowed)
__device__ int   g_expert[B_];
// Aggregated per-expert weights TRANSPOSED: [e][ocb(4)][m(2304)][ocl(64)]
__device__ float g_aggw[E_ * 4 * M_PER_OC * 64];

// ---------------------------------------------------------------------------
// Kernel 1: top-1 expert per sample (first-max semantics like jnp.argmax)
// ---------------------------------------------------------------------------
__global__ void expert_kernel(const float* __restrict__ scores) {
    int b = threadIdx.x;
    if (b < B_) {
        const float* s = scores + b * E_;
        float best = s[0];
        int bi = 0;
#pragma unroll
        for (int e = 1; e < E_; ++e) {
            float v = s[e];
            if (v > best) { best = v; bi = e; }
        }
        g_expert[b] = bi;
    }
}

// ---------------------------------------------------------------------------
// Kernel 2: aggw[e][ocb][m][ocl] = W[oc][m] + SCALING * sum_r B[e,3oc+m/768,r]*A[e,r,m%768]
// ---------------------------------------------------------------------------
__global__ void aggw_kernel(const float* __restrict__ weight,
                            const float* __restrict__ lora_A,
                            const float* __restrict__ lora_B) {
    int t = blockIdx.x * blockDim.x + threadIdx.x;   // 5*256*2304 = 2,949,120
    int m    = t % M_PER_OC;
    int rest = t / M_PER_OC;
    int oc   = rest % COUT_;
    int e    = rest / COUT_;
    if (e >= E_) return;

    int j = m / 768;   // ok = 3*oc + j
    int v = m % 768;   // ik

    const float* Bp = lora_B + e * 9216 + (3 * oc + j) * 12;
    const float* Ap = lora_A + e * 9216;

    float acc = 0.f;
#pragma unroll
    for (int r = 0; r < 12; ++r)
        acc += Bp[r] * Ap[r * 768 + v];

    float w = weight[oc * M_PER_OC + m];
    int ocb = oc >> 6, ocl = oc & 63;
    g_aggw[(((e * 4 + ocb) * M_PER_OC) + m) * 64 + ocl] = w + SCALING * acc;
}

// ---------------------------------------------------------------------------
// Packed fp32x2 helpers
// ---------------------------------------------------------------------------
__device__ __forceinline__ u64 dup2(float v) {
    u64 r;
    asm("mov.b64 %0, {%1,%1};" : "=l"(r) : "f"(v));
    return r;
}
__device__ __forceinline__ void fma2(u64& d, u64 a, u64 b) {
    asm("fma.rn.f32x2 %0, %1, %2, %0;" : "+l"(d) : "l"(a), "l"(b));
}
__device__ __forceinline__ float2 up2(u64 v) {
    float lo, hi;
    asm("mov.b64 {%0,%1}, %2;" : "=f"(lo), "=f"(hi) : "l"(v));
    return make_float2(lo, hi);
}
// LDS.128 delivering two aligned f32x2 pairs directly (no repacking MOVs)
__device__ __forceinline__ void lds_w2(u64& a, u64& b, unsigned addr) {
    asm("ld.shared.v2.u64 {%0,%1}, [%2];" : "=l"(a), "=l"(b) : "r"(addr));
}

// ---------------------------------------------------------------------------
// Kernel 3: direct conv. Grid (49 tiles, 4 ocb, 32 b), 64 threads.
// CTA: 64 oc x 8x8 px. Thread: 8 oc (4 f32x2 pairs) x 8 px (one row).
// ---------------------------------------------------------------------------
__global__ __launch_bounds__(64)
void conv_kernel(const float* __restrict__ x, float* __restrict__ out) {
    __shared__ __align__(16) float w_s[CI_TILE * 9 * 64];   // [m][oc], 18 KB
    __shared__ __align__(16) float x_s[CI_TILE * 10 * 12];  // [ci][10 rows][12], 3.75 KB

    const int tile = blockIdx.x;          // 0..48
    const int ocb  = blockIdx.y;          // 0..3
    const int b    = blockIdx.z;          // 0..31
    const int gy0  = (tile / 7) * 8;
    const int gx0  = (tile % 7) * 8;
    const int e    = g_expert[b];
    const int tid  = threadIdx.x;

    const int chid = tid & 7;             // 8 oc-slots
    const int row  = tid >> 3;            // 8 row-slots
    const int oc0  = chid * 8;

    const float* xb = x + (long long)b * CIN_ * HW;
    const float* wg = g_aggw + (long long)(e * 4 + ocb) * M_PER_OC * 64;

    u64 acc[32];
#pragma unroll
    for (int i = 0; i < 32; ++i) acc[i] = 0ULL;

    const unsigned w_sbase = (unsigned)__cvta_generic_to_shared(w_s) + oc0 * 4;
    const float* xrow_base = x_s + row * 12;

    for (int ci0 = 0; ci0 < CIN_; ci0 += CI_TILE) {
        // --- weight slab: 72 m-rows x 64 oc = 4608 floats (1152 float4, coalesced)
        const float4* wg4 = (const float4*)(wg + ci0 * 9 * 64);
        float4* ws4 = (float4*)w_s;
#pragma unroll
        for (int i = 0; i < 18; ++i)
            ws4[tid + i * 64] = wg4[tid + i * 64];

        // --- x slab: 8 ci x 10 x 10 halo in 8 x 10 x 12 padded layout (960 slots)
#pragma unroll
        for (int i = 0; i < 15; ++i) {
            int idx = tid + i * 64;
            int ci  = idx / 120;
            int rem = idx - ci * 120;
            int rr  = rem / 12;
            int cc  = rem - rr * 12;
            int gy  = gy0 - 1 + rr;
            int gx  = gx0 - 1 + cc;
            float val = 0.f;
            if (cc < 10 && gy >= 0 && gy < HH && gx >= 0 && gx < WW)
                val = xb[(ci0 + ci) * HW + gy * WW + gx];
            x_s[idx] = val;
        }
        __syncthreads();

#pragma unroll 1
        for (int ci = 0; ci < CI_TILE; ++ci) {
            const float* xp = xrow_base + ci * 120;
            const unsigned wbase = w_sbase + (ci * 9) * 256;   // 64 floats * 4B per m-row
#pragma unroll
            for (int k1 = 0; k1 < 3; ++k1) {
                // sliding window: 10 halo floats of this row, loaded as 3 LDS.128
                const float4* xq = (const float4*)(xp + k1 * 12);
                float4 q0 = xq[0], q1 = xq[1], q2 = xq[2];
                u64 xd[10];
                xd[0] = dup2(q0.x); xd[1] = dup2(q0.y);
                xd[2] = dup2(q0.z); xd[3] = dup2(q0.w);
                xd[4] = dup2(q1.x); xd[5] = dup2(q1.y);
                xd[6] = dup2(q1.z); xd[7] = dup2(q1.w);
                xd[8] = dup2(q2.x); xd[9] = dup2(q2.y);
#pragma unroll
                for (int k2 = 0; k2 < 3; ++k2) {
                    unsigned wa = wbase + (k1 * 3 + k2) * 256;
                    u64 wp0, wp1, wp2, wp3;
                    lds_w2(wp0, wp1, wa);
                    lds_w2(wp2, wp3, wa + 16);
#pragma unroll
                    for (int j = 0; j < 8; ++j) {
                        fma2(acc[j],      wp0, xd[k2 + j]);
                        fma2(acc[8 + j],  wp1, xd[k2 + j]);
                        fma2(acc[16 + j], wp2, xd[k2 + j]);
                        fma2(acc[24 + j], wp3, xd[k2 + j]);
                    }
                }
            }
        }
        __syncthreads();
    }

    // --- epilogue: 4 oc-pairs x 8 px; assemble float4 rows, STG.128
    const int y = gy0 + row;
#pragma unroll
    for (int p = 0; p < 4; ++p) {
        const int oc = ocb * 64 + oc0 + 2 * p;
        float2 a0 = up2(acc[p * 8 + 0]), a1 = up2(acc[p * 8 + 1]);
        float2 a2 = up2(acc[p * 8 + 2]), a3 = up2(acc[p * 8 + 3]);
        float2 a4 = up2(acc[p * 8 + 4]), a5 = up2(acc[p * 8 + 5]);
        float2 a6 = up2(acc[p * 8 + 6]), a7 = up2(acc[p * 8 + 7]);
        float* o0 = out + (((long long)b * COUT_ + oc) * HH + y) * WW + gx0;
        float* o1 = o0 + HW;
        ((float4*)o0)[0] = make_float4(a0.x, a1.x, a2.x, a3.x);
        ((float4*)o0)[1] = make_float4(a4.x, a5.x, a6.x, a7.x);
        ((float4*)o1)[0] = make_float4(a0.y, a1.y, a2.y, a3.y);
        ((float4*)o1)[1] = make_float4(a4.y, a5.y, a6.y, a7.y);
    }
}

// ---------------------------------------------------------------------------
extern "C" void kernel_launch(void* const* d_in, const int* in_sizes, int n_in,
                              void* d_out, int out_size) {
    const float* x      = (const float*)d_in[0];
    const float* scores = (const float*)d_in[1];
    const float* weight = (const float*)d_in[2];
    const float* lora_A = (const float*)d_in[3];
    const float* lora_B = (const float*)d_in[4];
    float* out = (float*)d_out;

    expert_kernel<<<1, 32>>>(scores);

    int total = E_ * COUT_ * M_PER_OC;           // 2,949,120
    aggw_kernel<<<total / 256, 256>>>(weight, lora_A, lora_B);

    dim3 grid(49, 4, B_);
    conv_kernel<<<grid, 64>>>(x, out);
}

// round 6
// speedup vs baseline: 1.3666x; 1.1220x over previous
#include <cuda_runtime.h>
#include <cuda_bf16.h>
#include <cstdint>

// ---------------- problem constants ----------------
#define B_      32
#define E_      5
#define CIN_    256
#define COUT_   256
#define HH      56
#define WW      56
#define HW      (HH * WW)        // 3136
#define M_PER_OC 2304
#define NP      3364             // 58*58 padded pixels
#define KCH     108              // K chunks of 64 (9 shifts * 12 blocks)
#define NTILES  13

// SMEM layout for conv kernel
#define A_TILE_B 16384           // 128 rows * 128B
#define B_TILE_B 32768           // 256 rows * 128B
#define STAGE_B  (A_TILE_B + B_TILE_B)   // 49152
#define SMEM_TOTAL (2 * STAGE_B)         // 98304

typedef unsigned long long u64;

// ---------------- device globals (no cudaMalloc allowed) ----------------
__device__ int g_expert[B_];
// A matrix: [e][ocb][128 oc][6912 k] bf16, k = (k1k2*12 + cq*3 + kb)*64 + cl
__device__ __nv_bfloat16 g_A[(size_t)E_ * 2 * 128 * 6912];
// padded transposed input: [b][n 3364][c 512] (c: 0-255 hi, 256-511 lo)
__device__ __nv_bfloat16 g_xpt[(size_t)B_ * NP * 512];

// ---------------- helpers ----------------
__device__ __forceinline__ unsigned SWZ(unsigned off) {
    return off ^ ((off >> 3) & 0x70);
}

__device__ __forceinline__ void cpa16(unsigned dst, const void* src, unsigned srcsize) {
    asm volatile("cp.async.ca.shared.global [%0], [%1], 16, %2;\n"
                 :: "r"(dst), "l"(src), "r"(srcsize) : "memory");
}

__device__ __forceinline__ void ldsm_x4(unsigned* r, unsigned addr) {
    asm volatile("ldmatrix.sync.aligned.m8n8.x4.shared.b16 {%0,%1,%2,%3}, [%4];"
                 : "=r"(r[0]), "=r"(r[1]), "=r"(r[2]), "=r"(r[3]) : "r"(addr));
}

__device__ __forceinline__ void mma_bf16(float* d, const unsigned* a,
                                         unsigned b0, unsigned b1) {
    asm volatile(
        "mma.sync.aligned.m16n8k16.row.col.f32.bf16.bf16.f32 "
        "{%0,%1,%2,%3}, {%4,%5,%6,%7}, {%8,%9}, {%0,%1,%2,%3};"
        : "+f"(d[0]), "+f"(d[1]), "+f"(d[2]), "+f"(d[3])
        : "r"(a[0]), "r"(a[1]), "r"(a[2]), "r"(a[3]), "r"(b0), "r"(b1));
}

// ---------------------------------------------------------------------------
// Kernel 1: top-1 expert per sample
// ---------------------------------------------------------------------------
__global__ void expert_kernel(const float* __restrict__ scores) {
    int b = threadIdx.x;
    if (b < B_) {
        const float* s = scores + b * E_;
        float best = s[0];
        int bi = 0;
#pragma unroll
        for (int e = 1; e < E_; ++e) {
            float v = s[e];
            if (v > best) { best = v; bi = e; }
        }
        g_expert[b] = bi;
    }
}

// ---------------------------------------------------------------------------
// Kernel 2: build A matrix (agg weight -> bf16 hi/lo, K-ordered for chunks)
// ---------------------------------------------------------------------------
__global__ void abuild_kernel(const float* __restrict__ weight,
                              const float* __restrict__ lora_A,
                              const float* __restrict__ lora_B) {
    int t = blockIdx.x * blockDim.x + threadIdx.x;   // 5*256*2304
    int m    = t % M_PER_OC;
    int rest = t / M_PER_OC;
    int oc   = rest % COUT_;
    int e    = rest / COUT_;
    if (e >= E_) return;

    int j = m / 768, v = m % 768;
    const float* Bp = lora_B + e * 9216 + (3 * oc + j) * 12;
    const float* Ap = lora_A + e * 9216;
    float acc = 0.f;
#pragma unroll
    for (int r = 0; r < 12; ++r) acc += Bp[r] * Ap[r * 768 + v];
    float val = weight[oc * M_PER_OC + m] + 4.0f * acc;

    __nv_bfloat16 hi = __float2bfloat16(val);
    __nv_bfloat16 lo = __float2bfloat16(val - __bfloat162float(hi));

    int ci = m / 9, kk = m % 9;          // kk = k1*3+k2
    int ocb = oc >> 7, ocl = oc & 127;
    int cq = ci >> 6, cl = ci & 63;
    __nv_bfloat16* arow = g_A + ((size_t)(e * 2 + ocb) * 128 + ocl) * 6912;
    int kb_base = kk * 12 + cq * 3;
    arow[(kb_base + 0) * 64 + cl] = hi;   // pairs x_hi
    arow[(kb_base + 1) * 64 + cl] = hi;   // pairs x_lo
    arow[(kb_base + 2) * 64 + cl] = lo;   // pairs x_hi
}

// ---------------------------------------------------------------------------
// Kernel 3: padded, transposed, bf16-split input xp_t[b][n][c]
// ---------------------------------------------------------------------------
__global__ void xprep_kernel(const float* __restrict__ x) {
    __shared__ float tile[64 * 58];
    int cblk = blockIdx.x, y58 = blockIdx.y, b = blockIdx.z;
    int tid = threadIdx.x;
    int y = y58 - 1;
    if (y >= 0 && y < HH) {
        for (int idx = tid; idx < 64 * 58; idx += 256) {
            int c = idx / 58, px = idx % 58;
            int xx = px - 1;
            float v = 0.f;
            if (xx >= 0 && xx < WW)
                v = x[((size_t)(b * CIN_ + cblk * 64 + c)) * HW + y * WW + xx];
            tile[idx] = v;
        }
    } else {
        for (int idx = tid; idx < 64 * 58; idx += 256) tile[idx] = 0.f;
    }
    __syncthreads();
    __nv_bfloat16* dst = g_xpt + ((size_t)b * NP + y58 * 58) * 512 + cblk * 64;
    for (int idx = tid; idx < 58 * 64; idx += 256) {
        int px = idx >> 6, c = idx & 63;
        float v = tile[c * 58 + px];
        __nv_bfloat16 hi = __float2bfloat16(v);
        __nv_bfloat16 lo = __float2bfloat16(v - __bfloat162float(hi));
        dst[(size_t)px * 512 + c] = hi;
        dst[(size_t)px * 512 + 256 + c] = lo;
    }
}

// ---------------------------------------------------------------------------
// K-chunk loader: A 128x64 bf16, B 256x64 bf16, SW128, cp.async (256 threads)
// ---------------------------------------------------------------------------
__device__ __forceinline__ void load_chunk(int q, unsigned stage,
                                           const __nv_bfloat16* Abase,
                                           const __nv_bfloat16* Bbase,
                                           int n0, int tid) {
    int k1k2 = q / 12, r = q % 12, cq = r / 3, kb = r % 3;
    int shift = (k1k2 / 3) * 58 + (k1k2 % 3);
    int c0 = ((kb == 1) ? 256 : 0) + cq * 64;
    // A tile: 128 rows x 128B; threads 0-127, one row each
    if (tid < 128) {
        const char* arow = (const char*)(Abase + (size_t)tid * 6912 + q * 64);
#pragma unroll
        for (int u = 0; u < 8; ++u)
            cpa16(stage + SWZ(tid * 128 + u * 16), arow + u * 16, 16);
    }
    // B tile: 256 rows x 128B; one row per thread
    {
        unsigned bs = stage + A_TILE_B;
        int n = n0 + shift + tid;
        bool ok = (n < NP);
        const char* src = ok ? (const char*)(Bbase + (size_t)n * 512 + c0)
                             : (const char*)Bbase;
        unsigned sz = ok ? 16u : 0u;
#pragma unroll
        for (int u = 0; u < 8; ++u)
            cpa16(bs + SWZ(tid * 128 + u * 16), src + u * 16, sz);
    }
    asm volatile("cp.async.commit_group;" ::: "memory");
}

// ---------------------------------------------------------------------------
// Kernel 4: HMMA implicit-GEMM conv. grid (13, 2, 32), 256 threads.
// CTA: 128 oc x 256 px. Warp grid 2(M)x4(N), warp tile 64x64.
// ---------------------------------------------------------------------------
__global__ __launch_bounds__(256, 1)
void conv_mma_kernel(float* __restrict__ out) {
    extern __shared__ __align__(1024) char smem[];
    const unsigned sbase = (unsigned)__cvta_generic_to_shared(smem);
    const int tid  = threadIdx.x;
    const int lane = tid & 31, wid = tid >> 5;
    const int n0   = blockIdx.x * 256;
    const int ocb  = blockIdx.y;
    const int b    = blockIdx.z;
    const int e    = g_expert[b];

    const __nv_bfloat16* Abase = g_A + (size_t)(e * 2 + ocb) * 128 * 6912;
    const __nv_bfloat16* Bbase = g_xpt + (size_t)b * NP * 512;

    float acc[128];
#pragma unroll
    for (int i = 0; i < 128; ++i) acc[i] = 0.f;

    // warp / lane geometry
    const int wm = wid & 1, wn = wid >> 1;      // 2 x 4 warps
    const int m0 = wm * 64, n0w = wn * 64;
    const int g  = lane >> 3, lr = lane & 7;
    // A frag addressing: g0:(m-lo,k-lo) g1:(m-hi,k-lo) g2:(m-lo,k-hi) g3:(m-hi,k-hi)
    const unsigned a_off0 = (unsigned)((m0 + (g & 1) * 8 + lr) * 128 + (g >> 1) * 16);
    // B frag addressing: g0:(n-lo,k-lo) g1:(n-lo,k-hi) g2:(n-hi,k-lo) g3:(n-hi,k-hi)
    const unsigned b_off0 = (unsigned)((n0w + (g >> 1) * 8 + lr) * 128 + (g & 1) * 16);

    // prologue
    load_chunk(0, sbase,           Abase, Bbase, n0, tid);
    load_chunk(1, sbase + STAGE_B, Abase, Bbase, n0, tid);

    for (int q = 0; q < KCH; ++q) {
        const int s = q & 1;
        const unsigned st = sbase + s * STAGE_B;
        asm volatile("cp.async.wait_group 1;" ::: "memory");
        __syncthreads();

#pragma unroll
        for (int ks = 0; ks < 4; ++ks) {
            unsigned ar[16], br[16];
#pragma unroll
            for (int mt = 0; mt < 4; ++mt)
                ldsm_x4(ar + mt * 4, st + SWZ(a_off0 + mt * 2048 + ks * 32));
#pragma unroll
            for (int ntp = 0; ntp < 4; ++ntp)
                ldsm_x4(br + ntp * 4,
                        st + A_TILE_B + SWZ(b_off0 + ntp * 2048 + ks * 32));
#pragma unroll
            for (int mt = 0; mt < 4; ++mt)
#pragma unroll
                for (int nt = 0; nt < 8; ++nt) {
                    int bi = (nt >> 1) * 4 + (nt & 1) * 2;
                    mma_bf16(acc + (mt * 8 + nt) * 4, ar + mt * 4,
                             br[bi], br[bi + 1]);
                }
        }
        __syncthreads();
        if (q + 2 < KCH)
            load_chunk(q + 2, st, Abase, Bbase, n0, tid);
    }

    // --- epilogue: predicated direct stores ---
    const int qrow = lane >> 2;
    const int qc   = (lane & 3) * 2;
    const size_t ob = (size_t)b * COUT_ * HW;
#pragma unroll
    for (int mt = 0; mt < 4; ++mt) {
        const int mA = ocb * 128 + m0 + mt * 16 + qrow;
        const int mB = mA + 8;
#pragma unroll
        for (int nt = 0; nt < 8; ++nt) {
            const float* a4 = acc + (mt * 8 + nt) * 4;
            int p0 = n0 + n0w + nt * 8 + qc;
            int p1 = p0 + 1;
            int y0 = p0 / 58, x0 = p0 % 58;
            int y1 = p1 / 58, x1 = p1 % 58;
            bool v0 = (y0 < HH) && (x0 < WW);
            bool v1 = (y1 < HH) && (x1 < WW);
            if (v0) out[ob + ((size_t)mA * HH + y0) * WW + x0] = a4[0];
            if (v1) out[ob + ((size_t)mA * HH + y1) * WW + x1] = a4[1];
            if (v0) out[ob + ((size_t)mB * HH + y0) * WW + x0] = a4[2];
            if (v1) out[ob + ((size_t)mB * HH + y1) * WW + x1] = a4[3];
        }
    }
}

// ---------------------------------------------------------------------------
extern "C" void kernel_launch(void* const* d_in, const int* in_sizes, int n_in,
                              void* d_out, int out_size) {
    const float* x      = (const float*)d_in[0];
    const float* scores = (const float*)d_in[1];
    const float* weight = (const float*)d_in[2];
    const float* lora_A = (const float*)d_in[3];
    const float* lora_B = (const float*)d_in[4];
    float* out = (float*)d_out;

    cudaFuncSetAttribute(conv_mma_kernel,
                         cudaFuncAttributeMaxDynamicSharedMemorySize, SMEM_TOTAL);

    expert_kernel<<<1, 32>>>(scores);

    int total = E_ * COUT_ * M_PER_OC;          // 2,949,120
    abuild_kernel<<<total / 256, 256>>>(weight, lora_A, lora_B);

    dim3 xg(4, 58, B_);
    xprep_kernel<<<xg, 256>>>(x);

    dim3 cg(NTILES, 2, B_);
    conv_mma_kernel<<<cg, 256, SMEM_TOTAL>>>(out);
}

// round 7
// speedup vs baseline: 1.6203x; 1.1856x over previous
#include <cuda_runtime.h>
#include <cuda_bf16.h>
#include <cstdint>

// ---------------- problem constants ----------------
#define B_      32
#define E_      5
#define CIN_    256
#define COUT_   256
#define HH      56
#define WW      56
#define HW      (HH * WW)        // 3136
#define M_PER_OC 2304
#define NP      3364             // 58*58 padded pixels
#define KCH     108              // K chunks of 64 (9 shifts * 12 blocks)
#define NTILES  13

// SMEM layout for conv kernel: 4-stage pipeline
#define A_TILE_B 16384           // 128 rows * 128B
#define B_TILE_B 32768           // 256 rows * 128B
#define STAGE_B  (A_TILE_B + B_TILE_B)   // 49152
#define NSTAGE   4
#define SMEM_TOTAL (NSTAGE * STAGE_B)    // 196608

typedef unsigned long long u64;

// ---------------- device globals (no cudaMalloc allowed) ----------------
__device__ int g_expert[B_];
// A matrix: [e][ocb][128 oc][6912 k] bf16, k = (k1k2*12 + cq*3 + kb)*64 + cl
__device__ __nv_bfloat16 g_A[(size_t)E_ * 2 * 128 * 6912];
// padded transposed input: [b][n 3364][c 512] (c: 0-255 hi, 256-511 lo)
__device__ __nv_bfloat16 g_xpt[(size_t)B_ * NP * 512];

// ---------------- helpers ----------------
__device__ __forceinline__ unsigned SWZ(unsigned off) {
    return off ^ ((off >> 3) & 0x70);
}

__device__ __forceinline__ void cpa16(unsigned dst, const void* src, unsigned srcsize) {
    asm volatile("cp.async.ca.shared.global [%0], [%1], 16, %2;\n"
                 :: "r"(dst), "l"(src), "r"(srcsize) : "memory");
}

__device__ __forceinline__ void ldsm_x4(unsigned* r, unsigned addr) {
    asm volatile("ldmatrix.sync.aligned.m8n8.x4.shared.b16 {%0,%1,%2,%3}, [%4];"
                 : "=r"(r[0]), "=r"(r[1]), "=r"(r[2]), "=r"(r[3]) : "r"(addr));
}

__device__ __forceinline__ void mma_bf16(float* d, const unsigned* a,
                                         unsigned b0, unsigned b1) {
    asm volatile(
        "mma.sync.aligned.m16n8k16.row.col.f32.bf16.bf16.f32 "
        "{%0,%1,%2,%3}, {%4,%5,%6,%7}, {%8,%9}, {%0,%1,%2,%3};"
        : "+f"(d[0]), "+f"(d[1]), "+f"(d[2]), "+f"(d[3])
        : "r"(a[0]), "r"(a[1]), "r"(a[2]), "r"(a[3]), "r"(b0), "r"(b1));
}

// ---------------------------------------------------------------------------
// Kernel 1: top-1 expert per sample
// ---------------------------------------------------------------------------
__global__ void expert_kernel(const float* __restrict__ scores) {
    int b = threadIdx.x;
    if (b < B_) {
        const float* s = scores + b * E_;
        float best = s[0];
        int bi = 0;
#pragma unroll
        for (int e = 1; e < E_; ++e) {
            float v = s[e];
            if (v > best) { best = v; bi = e; }
        }
        g_expert[b] = bi;
    }
}

// ---------------------------------------------------------------------------
// Kernel 2: build A matrix (agg weight -> bf16 hi/lo, K-ordered for chunks)
// ---------------------------------------------------------------------------
__global__ void abuild_kernel(const float* __restrict__ weight,
                              const float* __restrict__ lora_A,
                              const float* __restrict__ lora_B) {
    int t = blockIdx.x * blockDim.x + threadIdx.x;   // 5*256*2304
    int m    = t % M_PER_OC;
    int rest = t / M_PER_OC;
    int oc   = rest % COUT_;
    int e    = rest / COUT_;
    if (e >= E_) return;

    int j = m / 768, v = m % 768;
    const float* Bp = lora_B + e * 9216 + (3 * oc + j) * 12;
    const float* Ap = lora_A + e * 9216;
    float acc = 0.f;
#pragma unroll
    for (int r = 0; r < 12; ++r) acc += Bp[r] * Ap[r * 768 + v];
    float val = weight[oc * M_PER_OC + m] + 4.0f * acc;

    __nv_bfloat16 hi = __float2bfloat16(val);
    __nv_bfloat16 lo = __float2bfloat16(val - __bfloat162float(hi));

    int ci = m / 9, kk = m % 9;          // kk = k1*3+k2
    int ocb = oc >> 7, ocl = oc & 127;
    int cq = ci >> 6, cl = ci & 63;
    __nv_bfloat16* arow = g_A + ((size_t)(e * 2 + ocb) * 128 + ocl) * 6912;
    int kb_base = kk * 12 + cq * 3;
    arow[(kb_base + 0) * 64 + cl] = hi;   // pairs x_hi
    arow[(kb_base + 1) * 64 + cl] = hi;   // pairs x_lo
    arow[(kb_base + 2) * 64 + cl] = lo;   // pairs x_hi
}

// ---------------------------------------------------------------------------
// Kernel 3: padded, transposed, bf16-split input xp_t[b][n][c]
// ---------------------------------------------------------------------------
__global__ void xprep_kernel(const float* __restrict__ x) {
    __shared__ float tile[64 * 58];
    int cblk = blockIdx.x, y58 = blockIdx.y, b = blockIdx.z;
    int tid = threadIdx.x;
    int y = y58 - 1;
    if (y >= 0 && y < HH) {
        for (int idx = tid; idx < 64 * 58; idx += 256) {
            int c = idx / 58, px = idx % 58;
            int xx = px - 1;
            float v = 0.f;
            if (xx >= 0 && xx < WW)
                v = x[((size_t)(b * CIN_ + cblk * 64 + c)) * HW + y * WW + xx];
            tile[idx] = v;
        }
    } else {
        for (int idx = tid; idx < 64 * 58; idx += 256) tile[idx] = 0.f;
    }
    __syncthreads();
    __nv_bfloat16* dst = g_xpt + ((size_t)b * NP + y58 * 58) * 512 + cblk * 64;
    for (int idx = tid; idx < 58 * 64; idx += 256) {
        int px = idx >> 6, c = idx & 63;
        float v = tile[c * 58 + px];
        __nv_bfloat16 hi = __float2bfloat16(v);
        __nv_bfloat16 lo = __float2bfloat16(v - __bfloat162float(hi));
        dst[(size_t)px * 512 + c] = hi;
        dst[(size_t)px * 512 + 256 + c] = lo;
    }
}

// ---------------------------------------------------------------------------
// K-chunk loader: A 128x64 bf16, B 256x64 bf16, SW128, cp.async
// Balanced: every thread issues 12 x 16B cp.async (A:4, B:8)
// ---------------------------------------------------------------------------
__device__ __forceinline__ void load_chunk(int q, unsigned stage,
                                           const __nv_bfloat16* Abase,
                                           const __nv_bfloat16* Bbase,
                                           int n0, int tid) {
    int k1k2 = q / 12, r = q % 12, cq = r / 3, kb = r % 3;
    int shift = (k1k2 / 3) * 58 + (k1k2 % 3);
    int c0 = ((kb == 1) ? 256 : 0) + cq * 64;
    // A tile: 128 rows x 128B; row = tid>>1, half-row per thread
    {
        int row = tid >> 1;
        int ub  = (tid & 1) * 4;
        const char* arow = (const char*)(Abase + (size_t)row * 6912 + q * 64);
#pragma unroll
        for (int u = 0; u < 4; ++u)
            cpa16(stage + SWZ(row * 128 + (ub + u) * 16), arow + (ub + u) * 16, 16);
    }
    // B tile: 256 rows x 128B; one row per thread
    {
        unsigned bs = stage + A_TILE_B;
        int n = n0 + shift + tid;
        bool ok = (n < NP);
        const char* src = ok ? (const char*)(Bbase + (size_t)n * 512 + c0)
                             : (const char*)Bbase;
        unsigned sz = ok ? 16u : 0u;
#pragma unroll
        for (int u = 0; u < 8; ++u)
            cpa16(bs + SWZ(tid * 128 + u * 16), src + u * 16, sz);
    }
    asm volatile("cp.async.commit_group;" ::: "memory");
}

// ---------------------------------------------------------------------------
// Kernel 4: HMMA implicit-GEMM conv. grid (13, 2, 32), 256 threads.
// CTA: 128 oc x 256 px. Warp grid 2(M)x4(N), warp tile 64x64.
// 4-stage cp.async pipeline, single sync per chunk, loads issued before MMA.
// ---------------------------------------------------------------------------
__global__ __launch_bounds__(256, 1)
void conv_mma_kernel(float* __restrict__ out) {
    extern __shared__ __align__(1024) char smem[];
    const unsigned sbase = (unsigned)__cvta_generic_to_shared(smem);
    const int tid  = threadIdx.x;
    const int lane = tid & 31, wid = tid >> 5;
    const int n0   = blockIdx.x * 256;
    const int ocb  = blockIdx.y;
    const int b    = blockIdx.z;
    const int e    = g_expert[b];

    const __nv_bfloat16* Abase = g_A + (size_t)(e * 2 + ocb) * 128 * 6912;
    const __nv_bfloat16* Bbase = g_xpt + (size_t)b * NP * 512;

    float acc[128];
#pragma unroll
    for (int i = 0; i < 128; ++i) acc[i] = 0.f;

    // warp / lane geometry
    const int wm = wid & 1, wn = wid >> 1;      // 2 x 4 warps
    const int m0 = wm * 64, n0w = wn * 64;
    const int g  = lane >> 3, lr = lane & 7;
    // A frag addressing: g0:(m-lo,k-lo) g1:(m-hi,k-lo) g2:(m-lo,k-hi) g3:(m-hi,k-hi)
    const unsigned a_off0 = (unsigned)((m0 + (g & 1) * 8 + lr) * 128 + (g >> 1) * 16);
    // B frag addressing: g0:(n-lo,k-lo) g1:(n-lo,k-hi) g2:(n-hi,k-lo) g3:(n-hi,k-hi)
    const unsigned b_off0 = (unsigned)((n0w + (g >> 1) * 8 + lr) * 128 + (g & 1) * 16);

    // prologue: fill 3 stages
    load_chunk(0, sbase,               Abase, Bbase, n0, tid);
    load_chunk(1, sbase + STAGE_B,     Abase, Bbase, n0, tid);
    load_chunk(2, sbase + 2 * STAGE_B, Abase, Bbase, n0, tid);

    for (int q = 0; q < KCH; ++q) {
        // ensure group q complete (tail-aware ladder)
        if (q < KCH - 2)
            asm volatile("cp.async.wait_group 2;" ::: "memory");
        else if (q == KCH - 2)
            asm volatile("cp.async.wait_group 1;" ::: "memory");
        else
            asm volatile("cp.async.wait_group 0;" ::: "memory");
        __syncthreads();

        // issue prefetch for q+3 into the stage drained at this barrier
        if (q + 3 < KCH)
            load_chunk(q + 3, sbase + ((q + 3) & 3) * STAGE_B,
                       Abase, Bbase, n0, tid);

        const unsigned st = sbase + (q & 3) * STAGE_B;
#pragma unroll
        for (int ks = 0; ks < 4; ++ks) {
            unsigned ar[16], br[16];
#pragma unroll
            for (int mt = 0; mt < 4; ++mt)
                ldsm_x4(ar + mt * 4, st + SWZ(a_off0 + mt * 2048 + ks * 32));
#pragma unroll
            for (int ntp = 0; ntp < 4; ++ntp)
                ldsm_x4(br + ntp * 4,
                        st + A_TILE_B + SWZ(b_off0 + ntp * 2048 + ks * 32));
#pragma unroll
            for (int mt = 0; mt < 4; ++mt)
#pragma unroll
                for (int nt = 0; nt < 8; ++nt) {
                    int bi = (nt >> 1) * 4 + (nt & 1) * 2;
                    mma_bf16(acc + (mt * 8 + nt) * 4, ar + mt * 4,
                             br[bi], br[bi + 1]);
                }
        }
    }

    // --- epilogue: predicated direct stores ---
    const int qrow = lane >> 2;
    const int qc   = (lane & 3) * 2;
    const size_t ob = (size_t)b * COUT_ * HW;
#pragma unroll
    for (int mt = 0; mt < 4; ++mt) {
        const int mA = ocb * 128 + m0 + mt * 16 + qrow;
        const int mB = mA + 8;
#pragma unroll
        for (int nt = 0; nt < 8; ++nt) {
            const float* a4 = acc + (mt * 8 + nt) * 4;
            int p0 = n0 + n0w + nt * 8 + qc;
            int p1 = p0 + 1;
            int y0 = p0 / 58, x0 = p0 % 58;
            int y1 = p1 / 58, x1 = p1 % 58;
            bool v0 = (y0 < HH) && (x0 < WW);
            bool v1 = (y1 < HH) && (x1 < WW);
            if (v0) out[ob + ((size_t)mA * HH + y0) * WW + x0] = a4[0];
            if (v1) out[ob + ((size_t)mA * HH + y1) * WW + x1] = a4[1];
            if (v0) out[ob + ((size_t)mB * HH + y0) * WW + x0] = a4[2];
            if (v1) out[ob + ((size_t)mB * HH + y1) * WW + x1] = a4[3];
        }
    }
}

// ---------------------------------------------------------------------------
extern "C" void kernel_launch(void* const* d_in, const int* in_sizes, int n_in,
                              void* d_out, int out_size) {
    const float* x      = (const float*)d_in[0];
    const float* scores = (const float*)d_in[1];
    const float* weight = (const float*)d_in[2];
    const float* lora_A = (const float*)d_in[3];
    const float* lora_B = (const float*)d_in[4];
    float* out = (float*)d_out;

    cudaFuncSetAttribute(conv_mma_kernel,
                         cudaFuncAttributeMaxDynamicSharedMemorySize, SMEM_TOTAL);

    expert_kernel<<<1, 32>>>(scores);

    int total = E_ * COUT_ * M_PER_OC;          // 2,949,120
    abuild_kernel<<<total / 256, 256>>>(weight, lora_A, lora_B);

    dim3 xg(4, 58, B_);
    xprep_kernel<<<xg, 256>>>(x);

    dim3 cg(NTILES, 2, B_);
    conv_mma_kernel<<<cg, 256, SMEM_TOTAL>>>(out);
}